// round 2
// baseline (speedup 1.0000x reference)
#include <cuda_runtime.h>
#include <math.h>

#define HH 512
#define WW 512
#define BB 8
#define NPIX (BB*HH*WW)        // 2097152
#define NKEY 4913              // 17^3
#define HALF 16

// ---------------- static device scratch (no allocations allowed) -------------
__device__ unsigned char  g_qidx[BB*3*HH*WW];     // mode-pooled bin index per (b,c,y,x)
__device__ unsigned short g_key [NPIX];           // joint triple key per (b,y,x)
__device__ unsigned int   g_hist[NKEY];           // joint histogram
__device__ float  g_A1[48],  g_B1[16];            // BN1-folded affine (xq -> h1 pre-lrelu)
__device__ float  g_A2[256], g_B2[16];            // BN2-folded affine (h1 -> prep pre-lrelu)
__device__ float  g_prepLUT[NKEY*16];             // prep values per key
__device__ float  g_d1[BB*16*171*171];
__device__ float  g_d2[BB*16*57*57];
__device__ float  g_d3[BB*16*19*19];
__device__ float  g_d4[BB*16*7*7];
__device__ float  g_d5[BB*16*3*3];
__device__ float  g_d6[BB*16*1*1];
__device__ double g_iterMom[6*16*5];              // per-iter per-group moments
__device__ float  g_S[192], g_T[192];             // folded BN scale/bias per iter*32ch

__device__ __forceinline__ const float* dlevel(int l){
    switch(l){
        case 1: return g_d1; case 2: return g_d2; case 3: return g_d3;
        case 4: return g_d4; case 5: return g_d5; default: return g_d6;
    }
}
__device__ __forceinline__ float* dlevelw(int l){
    switch(l){
        case 1: return g_d1; case 2: return g_d2; case 3: return g_d3;
        case 4: return g_d4; case 5: return g_d5; default: return g_d6;
    }
}

__device__ __forceinline__ int qbin(float v){
    // match jnp.round(x*255.0/16.0): two fp32 ops, round-half-even
    return (int)rintf(__fmul_rn(__fmul_rn(v, 255.0f), 0.0625f));
}

__device__ __forceinline__ unsigned char amax17(const unsigned int s[5]){
    int best = 0; unsigned int bc = s[0] & 255u;
    #pragma unroll
    for (int b = 1; b < 17; b++){
        unsigned int c = (s[b>>2] >> ((b&3)*8)) & 255u;
        if (c > bc){ bc = c; best = b; }   // strict > : first (smallest) max wins
    }
    return (unsigned char)best;
}

// ---------------- K0: zero accumulators --------------------------------------
__global__ void k_zero(){
    int i = blockIdx.x*blockDim.x + threadIdx.x;
    if (i < NKEY) g_hist[i] = 0u;
    if (i < 6*16*5) g_iterMom[i] = 0.0;
}

// ---------------- K1: 11x11 reflect-padded mode pool --------------------------
// block: (band of 32 rows, plane). 128 threads, 4 columns each.
// column histograms: 17 bins packed as 5 uint32 (8-bit lanes), per column.
__global__ void __launch_bounds__(128) k_mode(const float* __restrict__ x){
    const int plane = blockIdx.y;
    const int y0    = blockIdx.x * 32;
    const float* xp = x + (size_t)plane * 262144;
    unsigned char* qp = g_qidx + (size_t)plane * 262144;
    __shared__ unsigned int sh[5*512];
    const int tid = threadIdx.x;
    for (int i = tid; i < 5*512; i += 128) sh[i] = 0u;
    __syncthreads();
    const int c0 = tid * 4;
    // init window rows y0-5 .. y0+5 (reflected)
    for (int cc = 0; cc < 4; cc++){
        int col = c0 + cc;
        for (int dy = -5; dy <= 5; dy++){
            int ry = y0 + dy; ry = ry < 0 ? -ry : (ry > 511 ? 1022 - ry : ry);
            int b = qbin(xp[ry*512 + col]);
            sh[(b>>2)*512 + col] += 1u << ((b&3)*8);
        }
    }
    __syncthreads();
    for (int r = 0; r < 32; r++){
        int y = y0 + r;
        if (r > 0){
            int yr = y - 6; yr = yr < 0 ? -yr : yr;
            int ya = y + 5; ya = ya > 511 ? 1022 - ya : ya;
            for (int cc = 0; cc < 4; cc++){
                int col = c0 + cc;
                int br = qbin(xp[yr*512 + col]);
                int ba = qbin(xp[ya*512 + col]);
                sh[(br>>2)*512 + col] -= 1u << ((br&3)*8);
                sh[(ba>>2)*512 + col] += 1u << ((ba&3)*8);
            }
            __syncthreads();
        }
        unsigned int s[5];
        #pragma unroll
        for (int w = 0; w < 5; w++){
            unsigned int a = 0;
            #pragma unroll
            for (int j = -5; j <= 5; j++){
                int cj = c0 + j; cj = cj < 0 ? -cj : (cj > 511 ? 1022 - cj : cj);
                a += sh[w*512 + cj];
            }
            s[w] = a;
        }
        qp[y*512 + c0] = amax17(s);
        #pragma unroll
        for (int cc = 1; cc < 4; cc++){
            int c = c0 + cc;
            int cr = c - 6; cr = cr < 0 ? -cr : cr;
            int ca = c + 5; ca = ca > 511 ? 1022 - ca : ca;
            #pragma unroll
            for (int w = 0; w < 5; w++) s[w] += sh[w*512 + ca] - sh[w*512 + cr];
            qp[y*512 + c] = amax17(s);
        }
        __syncthreads();
    }
}

// ---------------- K2: joint key + histogram ----------------------------------
__global__ void k_keyhist(){
    __shared__ unsigned int h[NKEY];
    int tid = threadIdx.x;
    for (int i = tid; i < NKEY; i += 256) h[i] = 0u;
    __syncthreads();
    int stride = gridDim.x * 256;
    for (int p = blockIdx.x*256 + tid; p < NPIX; p += stride){
        int b = p >> 18, rem = p & 262143;
        int q0 = g_qidx[((b*3+0)<<18) + rem];
        int q1 = g_qidx[((b*3+1)<<18) + rem];
        int q2 = g_qidx[((b*3+2)<<18) + rem];
        int key = q0 + 17*q1 + 289*q2;
        g_key[p] = (unsigned short)key;
        atomicAdd(&h[key], 1u);
    }
    __syncthreads();
    for (int i = tid; i < NKEY; i += 256){
        unsigned int v = h[i];
        if (v) atomicAdd(&g_hist[i], v);
    }
}

// ---------------- K3: BN1 affine from histogram (analytic) -------------------
__global__ void k_bn1(const float* __restrict__ pw1, const float* __restrict__ pb1,
                      const float* __restrict__ g1,  const float* __restrict__ be1){
    int tid = threadIdx.x;
    double a[9]; for (int i=0;i<9;i++) a[i]=0.0;
    for (int t = tid; t < NKEY; t += 256){
        double w = (double)g_hist[t];
        if (w == 0.0) continue;
        double x0 = (double)(t % 17) * 0.0625;
        double x1 = (double)((t/17) % 17) * 0.0625;
        double x2 = (double)(t / 289) * 0.0625;
        a[0]+=w*x0; a[1]+=w*x1; a[2]+=w*x2;
        a[3]+=w*x0*x0; a[4]+=w*x0*x1; a[5]+=w*x0*x2;
        a[6]+=w*x1*x1; a[7]+=w*x1*x2; a[8]+=w*x2*x2;
    }
    __shared__ double red[256];
    __shared__ double mom[9];
    for (int m = 0; m < 9; m++){
        red[tid] = a[m]; __syncthreads();
        for (int off = 128; off; off >>= 1){
            if (tid < off) red[tid] += red[tid+off];
            __syncthreads();
        }
        if (tid == 0) mom[m] = red[0];
        __syncthreads();
    }
    if (tid < 16){
        int o = tid; const double N = (double)NPIX;
        double mu[3] = {mom[0]/N, mom[1]/N, mom[2]/N};
        double cov[3][3];
        cov[0][0]=mom[3]/N-mu[0]*mu[0]; cov[0][1]=mom[4]/N-mu[0]*mu[1]; cov[0][2]=mom[5]/N-mu[0]*mu[2];
        cov[1][1]=mom[6]/N-mu[1]*mu[1]; cov[1][2]=mom[7]/N-mu[1]*mu[2]; cov[2][2]=mom[8]/N-mu[2]*mu[2];
        cov[1][0]=cov[0][1]; cov[2][0]=cov[0][2]; cov[2][1]=cov[1][2];
        double wv[3] = {pw1[o*3], pw1[o*3+1], pw1[o*3+2]};
        double m = (double)pb1[o] + wv[0]*mu[0] + wv[1]*mu[1] + wv[2]*mu[2];
        double v = 0.0;
        for (int i = 0; i < 3; i++) for (int j = 0; j < 3; j++) v += wv[i]*wv[j]*cov[i][j];
        double inv = 1.0 / sqrt(v + 1e-5);
        double s = inv * (double)g1[o];
        g_A1[o*3+0]=(float)(wv[0]*s); g_A1[o*3+1]=(float)(wv[1]*s); g_A1[o*3+2]=(float)(wv[2]*s);
        g_B1[o]=(float)(((double)pb1[o]-m)*s + (double)be1[o]);
    }
}

// ---------------- K4: h1 moments over triples + BN2 affine -------------------
__global__ void k_bn2(const float* __restrict__ pw2, const float* __restrict__ pb2,
                      const float* __restrict__ g2,  const float* __restrict__ be2){
    __shared__ float sA1[48], sB1[16];
    __shared__ float h1s[256*16];
    __shared__ float ws[256];
    __shared__ double mom[152];
    __shared__ double mu[16];
    __shared__ double cov[16][16];
    int tid = threadIdx.x;
    if (tid < 48) sA1[tid] = g_A1[tid];
    if (tid < 16) sB1[tid] = g_B1[tid];
    __syncthreads();
    int pi = 0, pj = 0;
    if (tid >= 16 && tid < 152){
        int p = tid - 16, i = 0;
        while (p >= 16 - i){ p -= 16 - i; i++; }
        pi = i; pj = i + p;
    }
    double acc = 0.0;
    for (int base = 0; base < NKEY; base += 256){
        int tt = base + tid;
        float w = 0.f;
        if (tt < NKEY){
            w = (float)g_hist[tt];
            float x0 = (float)(tt % 17) * 0.0625f;
            float x1 = (float)((tt/17) % 17) * 0.0625f;
            float x2 = (float)(tt / 289) * 0.0625f;
            #pragma unroll
            for (int o = 0; o < 16; o++){
                float h = sB1[o] + sA1[o*3]*x0 + sA1[o*3+1]*x1 + sA1[o*3+2]*x2;
                h = h >= 0.f ? h : 0.01f*h;
                h1s[tid*16+o] = h;
            }
        }
        ws[tid] = w;
        __syncthreads();
        int cnt = NKEY - base; if (cnt > 256) cnt = 256;
        if (tid < 16){
            for (int k = 0; k < cnt; k++) acc += (double)ws[k] * (double)h1s[k*16+tid];
        } else if (tid < 152){
            for (int k = 0; k < cnt; k++)
                acc += (double)ws[k] * (double)h1s[k*16+pi] * (double)h1s[k*16+pj];
        }
        __syncthreads();
    }
    if (tid < 152) mom[tid] = acc;
    __syncthreads();
    const double N = (double)NPIX;
    if (tid < 16) mu[tid] = mom[tid] / N;
    __syncthreads();
    if (tid >= 16 && tid < 152){
        double c = mom[tid]/N - mu[pi]*mu[pj];
        cov[pi][pj] = c; cov[pj][pi] = c;
    }
    __syncthreads();
    if (tid < 16){
        int o = tid;
        double wv[16];
        double m = (double)pb2[o], v = 0.0;
        for (int i = 0; i < 16; i++){ wv[i] = pw2[o*16+i]; m += wv[i]*mu[i]; }
        for (int i = 0; i < 16; i++) for (int j = 0; j < 16; j++) v += wv[i]*wv[j]*cov[i][j];
        double inv = 1.0 / sqrt(v + 1e-5);
        double s = inv * (double)g2[o];
        for (int i = 0; i < 16; i++) g_A2[o*16+i] = (float)(wv[i]*s);
        g_B2[o] = (float)(((double)pb2[o]-m)*s + (double)be2[o]);
    }
}

// ---------------- K5: fill prep LUT -------------------------------------------
__global__ void k_prep(){
    int t = blockIdx.x*64 + threadIdx.x;
    if (t >= NKEY) return;
    float x0 = (float)(t % 17) * 0.0625f;
    float x1 = (float)((t/17) % 17) * 0.0625f;
    float x2 = (float)(t / 289) * 0.0625f;
    float h1[16];
    #pragma unroll
    for (int o = 0; o < 16; o++){
        float h = g_B1[o] + g_A1[o*3]*x0 + g_A1[o*3+1]*x1 + g_A1[o*3+2]*x2;
        h1[o] = h >= 0.f ? h : 0.01f*h;
    }
    #pragma unroll
    for (int o = 0; o < 16; o++){
        float pv = g_B2[o];
        #pragma unroll
        for (int i = 0; i < 16; i++) pv += g_A2[o*16+i]*h1[i];
        g_prepLUT[t*16+o] = pv >= 0.f ? pv : 0.01f*pv;
    }
}

// ---------------- K6: conv3x3 stride3 pad1 on prep (via key+LUT) -> d1 -------
__global__ void __launch_bounds__(192) k_conv1(const float* __restrict__ dw){
    __shared__ float sdw[2304];
    for (int i = threadIdx.x; i < 2304; i += 192) sdw[i] = dw[i];
    __syncthreads();
    int u = blockIdx.x, b = blockIdx.y;
    int v = threadIdx.x;
    if (v >= 171) return;
    float acc[16];
    #pragma unroll
    for (int o = 0; o < 16; o++) acc[o] = 0.f;
    for (int ky = 0; ky < 3; ky++){
        int iy = 3*u - 1 + ky; if (iy < 0 || iy >= 512) continue;
        for (int kx = 0; kx < 3; kx++){
            int ix = 3*v - 1 + kx; if (ix < 0 || ix >= 512) continue;
            int key = g_key[(b<<18) + iy*512 + ix];
            const float* pr = &g_prepLUT[key*16];
            #pragma unroll
            for (int c = 0; c < 16; c++){
                float pv = pr[c];
                #pragma unroll
                for (int o = 0; o < 16; o++)
                    acc[o] += sdw[(o*16+c)*9 + ky*3 + kx] * pv;
            }
        }
    }
    #pragma unroll
    for (int o = 0; o < 16; o++)
        g_d1[((b*16+o)*171 + u)*171 + v] = acc[o];
}

// ---------------- K7: generic conv3x3 stride3 pad1, d_l -> d_{l+1} -----------
__global__ void k_convN(int lin, int lout, int n, int m, const float* __restrict__ dw){
    __shared__ float sdw[2304];
    for (int i = threadIdx.x; i < 2304; i += 256) sdw[i] = dw[i];
    __syncthreads();
    const float* in = dlevel(lin);
    float* out = dlevelw(lout);
    int b = blockIdx.y;
    int pos = blockIdx.x*256 + threadIdx.x;
    if (pos >= m*m) return;
    int u = pos / m, v = pos % m;
    float acc[16];
    #pragma unroll
    for (int o = 0; o < 16; o++) acc[o] = 0.f;
    int nn = n*n;
    for (int ky = 0; ky < 3; ky++){
        int iy = 3*u - 1 + ky; if (iy < 0 || iy >= n) continue;
        for (int kx = 0; kx < 3; kx++){
            int ix = 3*v - 1 + kx; if (ix < 0 || ix >= n) continue;
            const float* ip = in + ((size_t)(b*16)*n + iy)*n + ix;
            #pragma unroll
            for (int c = 0; c < 16; c++){
                float pv = ip[c*nn];
                #pragma unroll
                for (int o = 0; o < 16; o++)
                    acc[o] += sdw[(o*16+c)*9 + ky*3 + kx] * pv;
            }
        }
    }
    #pragma unroll
    for (int o = 0; o < 16; o++)
        out[((b*16+o)*m + u)*m + v] = acc[o];
}

// ---------------- K8: per-iteration per-group moment stats --------------------
__global__ void __launch_bounds__(256) k_istats(){
    int iter = blockIdx.y >> 4, g = blockIdx.y & 15;
    const int n_all[7] = {512,171,57,19,7,3,1};
    int np = n_all[iter], nz = n_all[iter+1];
    const float* pprev = (iter > 0) ? dlevel(iter) : (const float*)0;
    const float* pz = dlevel(iter+1);
    int tid = threadIdx.x;
    float sp=0.f, sz=0.f, spp=0.f, szz=0.f, spz=0.f;
    int base = blockIdx.x * 8192;
    for (int k = 0; k < 32; k++){
        int p = base + k*256 + tid;
        int b = p >> 18, rem = p & 262143, y = rem >> 9, xx = rem & 511;
        float pv;
        if (iter == 0){
            pv = g_prepLUT[(int)g_key[p]*16 + g];
        } else {
            int r = (y*np) >> 9, c = (xx*np) >> 9;
            pv = pprev[((b*16+g)*np + r)*np + c];
        }
        int rz = (y*nz) >> 9, cz = (xx*nz) >> 9;
        float zv = pz[((b*16+g)*nz + rz)*nz + cz];
        sp += pv; sz += zv; spp += pv*pv; szz += zv*zv; spz += pv*zv;
    }
    #pragma unroll
    for (int off = 16; off; off >>= 1){
        sp  += __shfl_down_sync(0xffffffffu, sp,  off);
        sz  += __shfl_down_sync(0xffffffffu, sz,  off);
        spp += __shfl_down_sync(0xffffffffu, spp, off);
        szz += __shfl_down_sync(0xffffffffu, szz, off);
        spz += __shfl_down_sync(0xffffffffu, spz, off);
    }
    __shared__ float r[8][5];
    int w = tid >> 5, l = tid & 31;
    if (l == 0){ r[w][0]=sp; r[w][1]=sz; r[w][2]=spp; r[w][3]=szz; r[w][4]=spz; }
    __syncthreads();
    if (tid == 0){
        float a0=0,a1=0,a2=0,a3=0,a4=0;
        for (int i = 0; i < 8; i++){ a0+=r[i][0]; a1+=r[i][1]; a2+=r[i][2]; a3+=r[i][3]; a4+=r[i][4]; }
        int mb = (iter*16 + g)*5;
        atomicAdd(&g_iterMom[mb+0], (double)a0);
        atomicAdd(&g_iterMom[mb+1], (double)a1);
        atomicAdd(&g_iterMom[mb+2], (double)a2);
        atomicAdd(&g_iterMom[mb+3], (double)a3);
        atomicAdd(&g_iterMom[mb+4], (double)a4);
    }
}

// ---------------- K9: fold per-iter BN into scale/bias ------------------------
__global__ void k_affine(const float* __restrict__ sw, const float* __restrict__ gs,
                         const float* __restrict__ bs){
    int t = threadIdx.x;
    if (t >= 192) return;
    int iter = t / 32, ch = t % 32, g = ch >> 1, o = ch & 1;
    const double N = (double)NPIX;
    int mb = (iter*16 + g)*5;
    double mp  = g_iterMom[mb+0]/N, mz  = g_iterMom[mb+1]/N;
    double epp = g_iterMom[mb+2]/N, ezz = g_iterMom[mb+3]/N, epz = g_iterMom[mb+4]/N;
    double a = (double)sw[g*4 + o*2 + 0], b = (double)sw[g*4 + o*2 + 1];
    double mean = a*mp + b*mz;
    double m2 = a*a*epp + 2.0*a*b*epz + b*b*ezz;
    double var = m2 - mean*mean;
    double inv = 1.0 / sqrt(var + 1e-5);
    double s = (double)gs[ch] * inv;
    g_S[t] = (float)s;
    g_T[t] = (float)((double)bs[ch] - mean*s);
}

// ---------------- K10: fused final accumulate + write score -------------------
__global__ void __launch_bounds__(256) k_final(const float* __restrict__ sw,
                                               float* __restrict__ out){
    __shared__ float ssw[64], sS[192], sT[192];
    int tid = threadIdx.x;
    if (tid < 64) ssw[tid] = sw[tid];
    if (tid < 192){ sS[tid] = g_S[tid]; sT[tid] = g_T[tid]; }
    __syncthreads();
    int p = blockIdx.x*256 + tid;
    int b = p >> 18, rem = p & 262143, y = rem >> 9, xx = rem & 511;
    float prev[16];
    int key = g_key[p];
    const float4* pl = (const float4*)(g_prepLUT + key*16);
    float4 q0 = pl[0], q1 = pl[1], q2 = pl[2], q3 = pl[3];
    prev[0]=q0.x; prev[1]=q0.y; prev[2]=q0.z; prev[3]=q0.w;
    prev[4]=q1.x; prev[5]=q1.y; prev[6]=q1.z; prev[7]=q1.w;
    prev[8]=q2.x; prev[9]=q2.y; prev[10]=q2.z; prev[11]=q2.w;
    prev[12]=q3.x; prev[13]=q3.y; prev[14]=q3.z; prev[15]=q3.w;
    float sc[32];
    #pragma unroll
    for (int c = 0; c < 32; c++) sc[c] = 0.f;
    const int n_all[7] = {512,171,57,19,7,3,1};
    #pragma unroll
    for (int iter = 0; iter < 6; iter++){
        int nz = n_all[iter+1];
        const float* pz = dlevel(iter+1);
        int rz = (y*nz) >> 9, cz = (xx*nz) >> 9;
        const float* zb = pz + ((size_t)(b*16)*nz + rz)*nz + cz;
        int plane = nz*nz;
        #pragma unroll
        for (int g = 0; g < 16; g++){
            float zv = zb[g*plane];
            float pv = prev[g];
            float a0 = ssw[g*4+0], b0 = ssw[g*4+1];
            float a1 = ssw[g*4+2], b1 = ssw[g*4+3];
            int c0 = iter*32 + 2*g;
            float v0 = (a0*pv + b0*zv)*sS[c0]   + sT[c0];
            float v1 = (a1*pv + b1*zv)*sS[c0+1] + sT[c0+1];
            sc[2*g]   += v0 >= 0.f ? v0 : 0.01f*v0;
            sc[2*g+1] += v1 >= 0.f ? v1 : 0.01f*v1;
            prev[g] = zv;
        }
    }
    size_t ob = ((size_t)b*32) << 18;
    #pragma unroll
    for (int c = 0; c < 32; c++)
        out[ob + ((size_t)c << 18) + rem] = sc[c];
}

// ---------------- launcher ----------------------------------------------------
extern "C" void kernel_launch(void* const* d_in, const int* in_sizes, int n_in,
                              void* d_out, int out_size){
    const float* x   = (const float*)d_in[0];
    const float* pw1 = (const float*)d_in[1];
    const float* pb1 = (const float*)d_in[2];
    const float* g1  = (const float*)d_in[3];
    const float* be1 = (const float*)d_in[4];
    const float* pw2 = (const float*)d_in[5];
    const float* pb2 = (const float*)d_in[6];
    const float* g2  = (const float*)d_in[7];
    const float* be2 = (const float*)d_in[8];
    const float* dw  = (const float*)d_in[9];
    const float* sw  = (const float*)d_in[10];
    const float* gs  = (const float*)d_in[11];
    const float* bs  = (const float*)d_in[12];
    float* out = (float*)d_out;
    (void)in_sizes; (void)n_in; (void)out_size;

    k_zero<<<(NKEY+255)/256, 256>>>();
    k_mode<<<dim3(16, 24), 128>>>(x);
    k_keyhist<<<512, 256>>>();
    k_bn1<<<1, 256>>>(pw1, pb1, g1, be1);
    k_bn2<<<1, 256>>>(pw2, pb2, g2, be2);
    k_prep<<<(NKEY+63)/64, 64>>>();
    k_conv1<<<dim3(171, 8), 192>>>(dw);
    k_convN<<<dim3((57*57+255)/256, 8), 256>>>(1, 2, 171, 57, dw);
    k_convN<<<dim3((19*19+255)/256, 8), 256>>>(2, 3, 57, 19, dw);
    k_convN<<<dim3((7*7+255)/256, 8), 256>>>(3, 4, 19, 7, dw);
    k_convN<<<dim3((3*3+255)/256, 8), 256>>>(4, 5, 7, 3, dw);
    k_convN<<<dim3(1, 8), 256>>>(5, 6, 3, 1, dw);
    k_istats<<<dim3(256, 96), 256>>>();
    k_affine<<<1, 256>>>(sw, gs, bs);
    k_final<<<NPIX/256, 256>>>(sw, out);
}

// round 3
// speedup vs baseline: 1.4849x; 1.4849x over previous
#include <cuda_runtime.h>
#include <math.h>

#define NPIX 2097152
#define NKEY 4913

// double accumulator offsets
#define OF_XMOM 0
#define OF_M0P  16
#define OF_M0PP 32
#define OF_MOM2 48
#define OF_ZM   200
#define OF_ZM2  296
#define OF_PZ   392
#define ACCN    512

__device__ unsigned char  g_qidx[8*3*512*512];
__device__ unsigned short g_key [NPIX];
__device__ unsigned int   g_hist[NKEY];
__device__ double g_acc[ACCN];
__device__ float  g_A1[48],  g_B1[16];
__device__ float  g_A2[256], g_B2[16];
__device__ float  g_prepLUT[NKEY*16];
__device__ float  g_S[192], g_T[192];
// pyramid levels, CHANNEL-LAST: d[((b*n+y)*n+x)*16 + g]
__device__ float  g_d1[8*171*171*16];
__device__ float  g_d2[8*57*57*16];
__device__ float  g_d3[8*19*19*16];
__device__ float  g_d4[8*7*7*16];
__device__ float  g_d5[8*3*3*16];
__device__ float  g_d6[8*16];

__constant__ int c_n[7] = {512,171,57,19,7,3,1};

__device__ __forceinline__ const float* dlevel(int l){
    switch(l){ case 1: return g_d1; case 2: return g_d2; case 3: return g_d3;
               case 4: return g_d4; case 5: return g_d5; default: return g_d6; }
}
__device__ __forceinline__ float* dlevelw(int l){
    switch(l){ case 1: return g_d1; case 2: return g_d2; case 3: return g_d3;
               case 4: return g_d4; case 5: return g_d5; default: return g_d6; }
}
__device__ __forceinline__ int qbin(float v){
    return (int)rintf(__fmul_rn(__fmul_rn(v, 255.0f), 0.0625f));
}
__device__ __forceinline__ unsigned char amax17(const unsigned int s[5]){
    int best = 0; unsigned int bc = s[0] & 255u;
    #pragma unroll
    for (int b = 1; b < 17; b++){
        unsigned int c = (s[b>>2] >> ((b&3)*8)) & 255u;
        if (c > bc){ bc = c; best = b; }
    }
    return (unsigned char)best;
}
__device__ __forceinline__ void ld16(const float* p, float* v){
    const float4* q = (const float4*)p;
    float4 a=q[0], b=q[1], c=q[2], d=q[3];
    v[0]=a.x; v[1]=a.y; v[2]=a.z; v[3]=a.w; v[4]=b.x; v[5]=b.y; v[6]=b.z; v[7]=b.w;
    v[8]=c.x; v[9]=c.y; v[10]=c.z; v[11]=c.w; v[12]=d.x; v[13]=d.y; v[14]=d.z; v[15]=d.w;
}
__device__ __forceinline__ void st16(float* p, const float* v){
    float4* q = (float4*)p;
    q[0]=make_float4(v[0],v[1],v[2],v[3]);   q[1]=make_float4(v[4],v[5],v[6],v[7]);
    q[2]=make_float4(v[8],v[9],v[10],v[11]); q[3]=make_float4(v[12],v[13],v[14],v[15]);
}
// shuffle-reduce 16 lanes-local floats, accumulate into shared doubles sm[0..15]
__device__ __forceinline__ void red16(const float* a, double* sm){
    #pragma unroll
    for (int j = 0; j < 16; j++){
        float v = a[j];
        #pragma unroll
        for (int off = 16; off; off >>= 1) v += __shfl_down_sync(0xffffffffu, v, off);
        if ((threadIdx.x & 31) == 0 && v != 0.f) atomicAdd(&sm[j], (double)v);
    }
}
// fine pixels mapped to coarse row r of grid n: [ceil(r*512/n), ceil((r+1)*512/n))
__device__ __forceinline__ int wlo(int n, int r){ return (r*512 + n - 1)/n; }

// ---------------- K0: zero ----------------------------------------------------
__global__ void k_zero(){
    int i = blockIdx.x*blockDim.x + threadIdx.x;
    if (i < NKEY) g_hist[i] = 0u;
    if (i < ACCN) g_acc[i] = 0.0;
}

// ---------------- K1: 11x11 reflect mode pool ---------------------------------
__global__ void __launch_bounds__(128) k_mode(const float* __restrict__ x){
    const int plane = blockIdx.y;
    const int y0    = blockIdx.x * 32;
    const float* xp = x + (size_t)plane * 262144;
    unsigned char* qp = g_qidx + (size_t)plane * 262144;
    __shared__ unsigned int sh[5*512];
    const int tid = threadIdx.x;
    for (int i = tid; i < 5*512; i += 128) sh[i] = 0u;
    __syncthreads();
    const int c0 = tid * 4;
    for (int cc = 0; cc < 4; cc++){
        int col = c0 + cc;
        for (int dy = -5; dy <= 5; dy++){
            int ry = y0 + dy; ry = ry < 0 ? -ry : (ry > 511 ? 1022 - ry : ry);
            int b = qbin(xp[ry*512 + col]);
            sh[(b>>2)*512 + col] += 1u << ((b&3)*8);
        }
    }
    __syncthreads();
    for (int r = 0; r < 32; r++){
        int y = y0 + r;
        if (r > 0){
            int yr = y - 6; yr = yr < 0 ? -yr : yr;
            int ya = y + 5; ya = ya > 511 ? 1022 - ya : ya;
            for (int cc = 0; cc < 4; cc++){
                int col = c0 + cc;
                int br = qbin(xp[yr*512 + col]);
                int ba = qbin(xp[ya*512 + col]);
                sh[(br>>2)*512 + col] -= 1u << ((br&3)*8);
                sh[(ba>>2)*512 + col] += 1u << ((ba&3)*8);
            }
            __syncthreads();
        }
        unsigned int s[5];
        #pragma unroll
        for (int w = 0; w < 5; w++){
            unsigned int a = 0;
            #pragma unroll
            for (int j = -5; j <= 5; j++){
                int cj = c0 + j; cj = cj < 0 ? -cj : (cj > 511 ? 1022 - cj : cj);
                a += sh[w*512 + cj];
            }
            s[w] = a;
        }
        qp[y*512 + c0] = amax17(s);
        #pragma unroll
        for (int cc = 1; cc < 4; cc++){
            int c = c0 + cc;
            int cr = c - 6; cr = cr < 0 ? -cr : cr;
            int ca = c + 5; ca = ca > 511 ? 1022 - ca : ca;
            #pragma unroll
            for (int w = 0; w < 5; w++) s[w] += sh[w*512 + ca] - sh[w*512 + cr];
            qp[y*512 + c] = amax17(s);
        }
        __syncthreads();
    }
}

// ---------------- K2: keys + histogram + x-moments ----------------------------
__global__ void __launch_bounds__(256) k_keyhist(){
    __shared__ unsigned int h[NKEY];
    __shared__ float smw[8][9];
    int tid = threadIdx.x;
    for (int i = tid; i < NKEY; i += 256) h[i] = 0u;
    __syncthreads();
    int stride = gridDim.x * 256;
    for (int p = blockIdx.x*256 + tid; p < NPIX; p += stride){
        int b = p >> 18, rem = p & 262143;
        int q0 = g_qidx[((b*3+0)<<18) + rem];
        int q1 = g_qidx[((b*3+1)<<18) + rem];
        int q2 = g_qidx[((b*3+2)<<18) + rem];
        int key = q0 + 17*q1 + 289*q2;
        g_key[p] = (unsigned short)key;
        atomicAdd(&h[key], 1u);
    }
    __syncthreads();
    float m[9];
    #pragma unroll
    for (int j = 0; j < 9; j++) m[j] = 0.f;
    for (int i = tid; i < NKEY; i += 256){
        unsigned int v = h[i];
        if (v){
            atomicAdd(&g_hist[i], v);
            float w = (float)v;
            float x0 = (float)(i % 17) * 0.0625f;
            float x1 = (float)((i/17) % 17) * 0.0625f;
            float x2 = (float)(i / 289) * 0.0625f;
            m[0]+=w*x0; m[1]+=w*x1; m[2]+=w*x2;
            m[3]+=w*x0*x0; m[4]+=w*x0*x1; m[5]+=w*x0*x2;
            m[6]+=w*x1*x1; m[7]+=w*x1*x2; m[8]+=w*x2*x2;
        }
    }
    #pragma unroll
    for (int j = 0; j < 9; j++){
        float v = m[j];
        #pragma unroll
        for (int off = 16; off; off >>= 1) v += __shfl_down_sync(0xffffffffu, v, off);
        if ((tid & 31) == 0) smw[tid>>5][j] = v;
    }
    __syncthreads();
    if (tid < 9){
        float a = 0.f;
        for (int w8 = 0; w8 < 8; w8++) a += smw[w8][tid];
        if (a != 0.f) atomicAdd(&g_acc[OF_XMOM + tid], (double)a);
    }
}

// ---------------- K3: BN1 affine (tiny) ----------------------------------------
__global__ void k_bn1(const float* __restrict__ pw1, const float* __restrict__ pb1,
                      const float* __restrict__ g1,  const float* __restrict__ be1){
    int o = threadIdx.x;
    if (o >= 16) return;
    double mom[9];
    for (int i = 0; i < 9; i++) mom[i] = g_acc[OF_XMOM + i];
    const double N = (double)NPIX;
    double mu[3] = {mom[0]/N, mom[1]/N, mom[2]/N};
    double cov[3][3];
    cov[0][0]=mom[3]/N-mu[0]*mu[0]; cov[0][1]=mom[4]/N-mu[0]*mu[1]; cov[0][2]=mom[5]/N-mu[0]*mu[2];
    cov[1][1]=mom[6]/N-mu[1]*mu[1]; cov[1][2]=mom[7]/N-mu[1]*mu[2]; cov[2][2]=mom[8]/N-mu[2]*mu[2];
    cov[1][0]=cov[0][1]; cov[2][0]=cov[0][2]; cov[2][1]=cov[1][2];
    double wv[3] = {pw1[o*3], pw1[o*3+1], pw1[o*3+2]};
    double m = (double)pb1[o] + wv[0]*mu[0] + wv[1]*mu[1] + wv[2]*mu[2];
    double v = 0.0;
    for (int i = 0; i < 3; i++) for (int j = 0; j < 3; j++) v += wv[i]*wv[j]*cov[i][j];
    double s = (1.0 / sqrt(v + 1e-5)) * (double)g1[o];
    g_A1[o*3+0]=(float)(wv[0]*s); g_A1[o*3+1]=(float)(wv[1]*s); g_A1[o*3+2]=(float)(wv[2]*s);
    g_B1[o]=(float)(((double)pb1[o]-m)*s + (double)be1[o]);
}

// ---------------- K4a: h1 second moments (8 blocks, fp32 inner) ----------------
__global__ void __launch_bounds__(256) k_bn2a(){
    __shared__ float sA1[48], sB1[16];
    __shared__ float h1s[256*17];
    __shared__ float ws[256];
    int tid = threadIdx.x;
    if (tid < 48) sA1[tid] = g_A1[tid];
    if (tid < 16) sB1[tid] = g_B1[tid];
    __syncthreads();
    int pi = 0, pj = 0;
    if (tid >= 16 && tid < 152){
        int p = tid - 16, i = 0;
        while (p >= 16 - i){ p -= 16 - i; i++; }
        pi = i; pj = i + p;
    }
    int k0 = blockIdx.x * 615;
    int k1 = k0 + 615; if (k1 > NKEY) k1 = NKEY;
    double acc = 0.0;
    for (int base = k0; base < k1; base += 256){
        int tt = base + tid;
        float w = 0.f;
        if (tt < k1){
            w = (float)g_hist[tt];
            float x0 = (float)(tt % 17) * 0.0625f;
            float x1 = (float)((tt/17) % 17) * 0.0625f;
            float x2 = (float)(tt / 289) * 0.0625f;
            #pragma unroll
            for (int o = 0; o < 16; o++){
                float hh = sB1[o] + sA1[o*3]*x0 + sA1[o*3+1]*x1 + sA1[o*3+2]*x2;
                h1s[tid*17+o] = hh >= 0.f ? hh : 0.01f*hh;
            }
        }
        ws[tid] = w;
        __syncthreads();
        int cnt = k1 - base; if (cnt > 256) cnt = 256;
        float f0 = 0.f, f1 = 0.f;
        if (tid < 16){
            int k = 0;
            for (; k + 1 < cnt; k += 2){
                f0 += ws[k]   * h1s[k*17+tid];
                f1 += ws[k+1] * h1s[(k+1)*17+tid];
            }
            if (k < cnt) f0 += ws[k]*h1s[k*17+tid];
        } else if (tid < 152){
            int k = 0;
            for (; k + 1 < cnt; k += 2){
                f0 += ws[k]   * h1s[k*17+pi]     * h1s[k*17+pj];
                f1 += ws[k+1] * h1s[(k+1)*17+pi] * h1s[(k+1)*17+pj];
            }
            if (k < cnt) f0 += ws[k]*h1s[k*17+pi]*h1s[k*17+pj];
        }
        acc += (double)(f0 + f1);
        __syncthreads();
    }
    if (tid < 152 && acc != 0.0) atomicAdd(&g_acc[OF_MOM2 + tid], acc);
}

// ---------------- K4b: BN2 affine ----------------------------------------------
__global__ void k_bn2b(const float* __restrict__ pw2, const float* __restrict__ pb2,
                       const float* __restrict__ g2,  const float* __restrict__ be2){
    __shared__ double mu[16];
    __shared__ double cov[16][16];
    int tid = threadIdx.x;
    const double N = (double)NPIX;
    if (tid < 16) mu[tid] = g_acc[OF_MOM2 + tid] / N;
    __syncthreads();
    if (tid >= 16 && tid < 152){
        int p = tid - 16, i = 0;
        while (p >= 16 - i){ p -= 16 - i; i++; }
        int pi = i, pj = i + p;
        double c = g_acc[OF_MOM2 + tid]/N - mu[pi]*mu[pj];
        cov[pi][pj] = c; cov[pj][pi] = c;
    }
    __syncthreads();
    if (tid < 16){
        int o = tid;
        double wv[16];
        double m = (double)pb2[o], v = 0.0;
        for (int i = 0; i < 16; i++){ wv[i] = pw2[o*16+i]; m += wv[i]*mu[i]; }
        for (int i = 0; i < 16; i++) for (int j = 0; j < 16; j++) v += wv[i]*wv[j]*cov[i][j];
        double s = (1.0 / sqrt(v + 1e-5)) * (double)g2[o];
        for (int i = 0; i < 16; i++) g_A2[o*16+i] = (float)(wv[i]*s);
        g_B2[o] = (float)(((double)pb2[o]-m)*s + (double)be2[o]);
    }
}

// ---------------- K5: prep LUT + iter0 p-moments --------------------------------
__global__ void __launch_bounds__(256) k_prep(){
    __shared__ double sm[32];
    int tid = threadIdx.x;
    if (tid < 32) sm[tid] = 0.0;
    __syncthreads();
    int t = blockIdx.x*256 + tid;
    float s1[16], s2[16];
    if (t < NKEY){
        float w = (float)g_hist[t];
        float x0 = (float)(t % 17) * 0.0625f;
        float x1 = (float)((t/17) % 17) * 0.0625f;
        float x2 = (float)(t / 289) * 0.0625f;
        float h1[16];
        #pragma unroll
        for (int o = 0; o < 16; o++){
            float hh = g_B1[o] + g_A1[o*3]*x0 + g_A1[o*3+1]*x1 + g_A1[o*3+2]*x2;
            h1[o] = hh >= 0.f ? hh : 0.01f*hh;
        }
        float pv[16];
        #pragma unroll
        for (int o = 0; o < 16; o++){
            float p = g_B2[o];
            #pragma unroll
            for (int i = 0; i < 16; i++) p += g_A2[o*16+i]*h1[i];
            p = p >= 0.f ? p : 0.01f*p;
            pv[o] = p;
            s1[o] = w*p; s2[o] = w*p*p;
        }
        st16(g_prepLUT + t*16, pv);
    } else {
        #pragma unroll
        for (int o = 0; o < 16; o++){ s1[o] = 0.f; s2[o] = 0.f; }
    }
    red16(s1, sm);
    red16(s2, sm + 16);
    __syncthreads();
    if (tid < 16)       atomicAdd(&g_acc[OF_M0P  + tid],      sm[tid]);
    else if (tid < 32)  atomicAdd(&g_acc[OF_M0PP + tid - 16], sm[tid]);
}

// ---------------- K6: conv stride3 pad1 on prep(key,LUT) -> d1 ------------------
__global__ void __launch_bounds__(192) k_conv1(const float* __restrict__ dw){
    __shared__ float sdw[2304];
    for (int i = threadIdx.x; i < 2304; i += 192) sdw[i] = dw[i];
    __syncthreads();
    int u = blockIdx.x, b = blockIdx.y;
    int v = threadIdx.x;
    if (v >= 171) return;
    float acc[16];
    #pragma unroll
    for (int o = 0; o < 16; o++) acc[o] = 0.f;
    for (int ky = 0; ky < 3; ky++){
        int iy = 3*u - 1 + ky; if (iy < 0 || iy >= 512) continue;
        for (int kx = 0; kx < 3; kx++){
            int ix = 3*v - 1 + kx; if (ix < 0 || ix >= 512) continue;
            int key = g_key[(b<<18) + iy*512 + ix];
            float pv[16];
            ld16(g_prepLUT + key*16, pv);
            #pragma unroll
            for (int c = 0; c < 16; c++){
                #pragma unroll
                for (int o = 0; o < 16; o++)
                    acc[o] += sdw[(o*16+c)*9 + ky*3 + kx] * pv[c];
            }
        }
    }
    st16(g_d1 + ((size_t)(b*171+u)*171 + v)*16, acc);
}

// ---------------- K7: generic conv3x3 s3 p1, channel-last -----------------------
__global__ void k_convN(int lin, int lout, int n, int m, const float* __restrict__ dw){
    __shared__ float sdw[2304];
    for (int i = threadIdx.x; i < 2304; i += 256) sdw[i] = dw[i];
    __syncthreads();
    const float* in = dlevel(lin);
    float* out = dlevelw(lout);
    int b = blockIdx.y;
    int pos = blockIdx.x*256 + threadIdx.x;
    if (pos >= m*m) return;
    int u = pos / m, v = pos % m;
    float acc[16];
    #pragma unroll
    for (int o = 0; o < 16; o++) acc[o] = 0.f;
    for (int ky = 0; ky < 3; ky++){
        int iy = 3*u - 1 + ky; if (iy < 0 || iy >= n) continue;
        for (int kx = 0; kx < 3; kx++){
            int ix = 3*v - 1 + kx; if (ix < 0 || ix >= n) continue;
            float pv[16];
            ld16(in + ((size_t)(b*n+iy)*n + ix)*16, pv);
            #pragma unroll
            for (int c = 0; c < 16; c++){
                #pragma unroll
                for (int o = 0; o < 16; o++)
                    acc[o] += sdw[(o*16+c)*9 + ky*3 + kx] * pv[c];
            }
        }
    }
    st16(out + ((size_t)(b*m+u)*m + v)*16, acc);
}

// ---------------- K8: weighted z moments per level ------------------------------
__global__ void __launch_bounds__(256) k_zstats(){
    __shared__ double sm[32];
    int tid = threadIdx.x;
    if (tid < 32) sm[tid] = 0.0;
    __syncthreads();
    int lvl = blockIdx.z + 1;            // 1..6
    int n = c_n[lvl];
    int b = blockIdx.y;
    const float* dz = dlevel(lvl);
    int cells = n*n;
    float s1[16], s2[16];
    #pragma unroll
    for (int j = 0; j < 16; j++){ s1[j] = 0.f; s2[j] = 0.f; }
    for (int cell = blockIdx.x*256 + tid; cell < cells; cell += gridDim.x*256){
        int r = cell / n, c = cell % n;
        float w = (float)((wlo(n,r+1)-wlo(n,r)) * (wlo(n,c+1)-wlo(n,c)));
        float z[16];
        ld16(dz + ((size_t)(b*n+r)*n + c)*16, z);
        #pragma unroll
        for (int j = 0; j < 16; j++){ s1[j] += w*z[j]; s2[j] += w*z[j]*z[j]; }
    }
    red16(s1, sm); red16(s2, sm + 16);
    __syncthreads();
    if (tid < 16)       atomicAdd(&g_acc[OF_ZM  + (lvl-1)*16 + tid],      sm[tid]);
    else if (tid < 32)  atomicAdd(&g_acc[OF_ZM2 + (lvl-1)*16 + tid - 16], sm[tid]);
}

// ---------------- K9a: cross moments iters 1..5 (coarse pair scan) --------------
__global__ void __launch_bounds__(256) k_crossN(){
    __shared__ double sm[16];
    int tid = threadIdx.x;
    if (tid < 16) sm[tid] = 0.0;
    __syncthreads();
    int it = blockIdx.z + 1;             // iter 1..5
    int np = c_n[it], nz = c_n[it+1];
    int b = blockIdx.y;
    const float* dp = dlevel(it);
    const float* dz = dlevel(it+1);
    int cells = np*np;
    float acc[16];
    #pragma unroll
    for (int j = 0; j < 16; j++) acc[j] = 0.f;
    for (int cell = blockIdx.x*256 + tid; cell < cells; cell += gridDim.x*256){
        int r = cell / np, c = cell % np;
        float p[16];
        ld16(dp + ((size_t)(b*np+r)*np + c)*16, p);
        int y0 = wlo(np,r), y1 = wlo(np,r+1);
        int x0 = wlo(np,c), x1 = wlo(np,c+1);
        float zs[16];
        #pragma unroll
        for (int j = 0; j < 16; j++) zs[j] = 0.f;
        for (int y = y0; y < y1; y++){
            int s = (y*nz) >> 9;
            for (int xx = x0; xx < x1; xx++){
                int t = (xx*nz) >> 9;
                float z[16];
                ld16(dz + ((size_t)(b*nz+s)*nz + t)*16, z);
                #pragma unroll
                for (int j = 0; j < 16; j++) zs[j] += z[j];
            }
        }
        #pragma unroll
        for (int j = 0; j < 16; j++) acc[j] += p[j]*zs[j];
    }
    red16(acc, sm);
    __syncthreads();
    if (tid < 16) atomicAdd(&g_acc[OF_PZ + it*16 + tid], sm[tid]);
}

// ---------------- K9b: cross moment iter 0 (fine scan, LUT + d1) ----------------
__global__ void __launch_bounds__(256) k_cross0(){
    __shared__ double sm[16];
    int tid = threadIdx.x;
    if (tid < 16) sm[tid] = 0.0;
    __syncthreads();
    float acc[16];
    #pragma unroll
    for (int j = 0; j < 16; j++) acc[j] = 0.f;
    int stride = gridDim.x * 256;
    for (int p = blockIdx.x*256 + tid; p < NPIX; p += stride){
        int b = p >> 18, rem = p & 262143, y = rem >> 9, xx = rem & 511;
        int key = g_key[p];
        float pv[16], z[16];
        ld16(g_prepLUT + key*16, pv);
        int rz = (y*171) >> 9, cz = (xx*171) >> 9;
        ld16(g_d1 + ((size_t)(b*171+rz)*171 + cz)*16, z);
        #pragma unroll
        for (int j = 0; j < 16; j++) acc[j] += pv[j]*z[j];
    }
    red16(acc, sm);
    __syncthreads();
    if (tid < 16) atomicAdd(&g_acc[OF_PZ + tid], sm[tid]);
}

// ---------------- K10: fold per-iter BN into scale/bias --------------------------
__global__ void k_affine(const float* __restrict__ sw, const float* __restrict__ gs,
                         const float* __restrict__ bs){
    int t = threadIdx.x;
    if (t >= 192) return;
    int iter = t / 32, ch = t % 32, g = ch >> 1, o = ch & 1;
    const double N = (double)NPIX;
    double mp, mpp;
    if (iter == 0){ mp = g_acc[OF_M0P + g]; mpp = g_acc[OF_M0PP + g]; }
    else { mp = g_acc[OF_ZM + (iter-1)*16 + g]; mpp = g_acc[OF_ZM2 + (iter-1)*16 + g]; }
    double mz  = g_acc[OF_ZM  + iter*16 + g];
    double mzz = g_acc[OF_ZM2 + iter*16 + g];
    double mpz = g_acc[OF_PZ  + iter*16 + g];
    mp/=N; mpp/=N; mz/=N; mzz/=N; mpz/=N;
    double a = (double)sw[g*4 + o*2 + 0], b = (double)sw[g*4 + o*2 + 1];
    double mean = a*mp + b*mz;
    double m2 = a*a*mpp + 2.0*a*b*mpz + b*b*mzz;
    double var = m2 - mean*mean;
    double s = (double)gs[ch] * (1.0 / sqrt(var + 1e-5));
    g_S[t] = (float)s;
    g_T[t] = (float)((double)bs[ch] - mean*s);
}

// ---------------- K11: fused final accumulate + write ---------------------------
__global__ void __launch_bounds__(256) k_final(const float* __restrict__ sw,
                                               float* __restrict__ out){
    __shared__ float ssw[64], sS[192], sT[192];
    int tid = threadIdx.x;
    if (tid < 64) ssw[tid] = sw[tid];
    if (tid < 192){ sS[tid] = g_S[tid]; sT[tid] = g_T[tid]; }
    __syncthreads();
    int p = blockIdx.x*256 + tid;
    int b = p >> 18, rem = p & 262143, y = rem >> 9, xx = rem & 511;
    float prev[16];
    int key = g_key[p];
    ld16(g_prepLUT + key*16, prev);
    float sc[32];
    #pragma unroll
    for (int c = 0; c < 32; c++) sc[c] = 0.f;
    #pragma unroll
    for (int iter = 0; iter < 6; iter++){
        int nz = c_n[iter+1];
        int rz = (y*nz) >> 9, cz = (xx*nz) >> 9;
        float z[16];
        ld16(dlevel(iter+1) + ((size_t)(b*nz+rz)*nz + cz)*16, z);
        #pragma unroll
        for (int g = 0; g < 16; g++){
            float zv = z[g];
            float pv = prev[g];
            int c0 = iter*32 + 2*g;
            float v0 = (ssw[g*4+0]*pv + ssw[g*4+1]*zv)*sS[c0]   + sT[c0];
            float v1 = (ssw[g*4+2]*pv + ssw[g*4+3]*zv)*sS[c0+1] + sT[c0+1];
            sc[2*g]   += v0 >= 0.f ? v0 : 0.01f*v0;
            sc[2*g+1] += v1 >= 0.f ? v1 : 0.01f*v1;
            prev[g] = zv;
        }
    }
    size_t ob = ((size_t)b*32) << 18;
    #pragma unroll
    for (int c = 0; c < 32; c++)
        out[ob + ((size_t)c << 18) + rem] = sc[c];
}

// ---------------- launcher -------------------------------------------------------
extern "C" void kernel_launch(void* const* d_in, const int* in_sizes, int n_in,
                              void* d_out, int out_size){
    const float* x   = (const float*)d_in[0];
    const float* pw1 = (const float*)d_in[1];
    const float* pb1 = (const float*)d_in[2];
    const float* g1  = (const float*)d_in[3];
    const float* be1 = (const float*)d_in[4];
    const float* pw2 = (const float*)d_in[5];
    const float* pb2 = (const float*)d_in[6];
    const float* g2  = (const float*)d_in[7];
    const float* be2 = (const float*)d_in[8];
    const float* dw  = (const float*)d_in[9];
    const float* sw  = (const float*)d_in[10];
    const float* gs  = (const float*)d_in[11];
    const float* bs  = (const float*)d_in[12];
    float* out = (float*)d_out;
    (void)in_sizes; (void)n_in; (void)out_size;

    k_zero<<<20, 256>>>();
    k_mode<<<dim3(16, 24), 128>>>(x);
    k_keyhist<<<512, 256>>>();
    k_bn1<<<1, 32>>>(pw1, pb1, g1, be1);
    k_bn2a<<<8, 256>>>();
    k_bn2b<<<1, 256>>>(pw2, pb2, g2, be2);
    k_prep<<<20, 256>>>();
    k_conv1<<<dim3(171, 8), 192>>>(dw);
    k_convN<<<dim3(13, 8), 256>>>(1, 2, 171, 57, dw);
    k_convN<<<dim3(2, 8), 256>>>(2, 3, 57, 19, dw);
    k_convN<<<dim3(1, 8), 256>>>(3, 4, 19, 7, dw);
    k_convN<<<dim3(1, 8), 256>>>(4, 5, 7, 3, dw);
    k_convN<<<dim3(1, 8), 256>>>(5, 6, 3, 1, dw);
    k_zstats<<<dim3(115, 8, 6), 256>>>();
    k_crossN<<<dim3(115, 8, 5), 256>>>();
    k_cross0<<<2048, 256>>>();
    k_affine<<<1, 192>>>(sw, gs, bs);
    k_final<<<NPIX/256, 256>>>(sw, out);
}